// round 11
// baseline (speedup 1.0000x reference)
#include <cuda_runtime.h>
#include <cuda_fp16.h>

// APPNP, K=10. State g = norm ⊙ h kept in fp16 (row = 64 halves = 128B).
//   g_{t+1} = 0.9*norm^2 * (sum_{(s->v)} g_t[s]) + anchor,  anchor = 0.1*norm*feat
// Final: h = 0.9*norm*agg + 0.1*feat (fp32).
//
// Round 11: 4 nodes interleaved per warp. The ~23us/iter floor was invariant
// to bytes, instruction count, launches and waves -> binding constraint is
// per-warp outstanding loads (loop-carried id->row chain, MLP~2). Four
// independent node chains per warp issue 4 id + 4 row loads per loop
// iteration before any consumption -> structural MLP ~8. Exhausted chains
// read a zeroed dummy row (warp-uniform control flow, no pred

// -------------------------------------------------------------------------

#define NMAX  100000
#define DF    64
#define DF2   (DF / 2)
#define EMAX  1000000
#define EPAD  (EMAX + 4 * NMAX + 32)
#define KITER 10
#define TILE  256
#define NTILE ((NMAX + TILE - 1) / TILE)   // 391
#define NPW   4                            // nodes per warp, interleaved

__device__ uint4 g_a[(NMAX + 1) * 8];
__device__ uint4 g_b[(NMAX + 1) * 8];
__device__ uint4 g_anchor[(NMAX + 1) * 8];  // 0.1*norm*feat in fp16
__device__ float g_norm[NMAX];
__device__ int   g_deg[NMAX];
__device__ int   g_rowptr[NMAX + 1];        // padded-degree prefix
__device__ int   g_cursor[NMAX];
__device__ int   g_srcs[EPAD];
__device__ int   g_part[NTILE];

// ---------------------------------------------------------------- build ----

__global__ void k_zero(int n, int nthreads) {
    for (int i = blockIdx.x * blockDim.x + threadIdx.x; i < n; i += nthreads) {
        g_deg[i] = 0; g_cursor[i] = 0;
    }
}

__global__ void k_deg(const int* __restrict__ dst, int e, int nthreads) {
    for (int i = blockIdx.x * blockDim.x + threadIdx.x; i < e; i += nthreads)
        atomicAdd(&g_deg[dst[i]], 1);
}

__global__ void k_scan_part(int n) {
    __shared__ int sh[TILE];
    int t = threadIdx.x;
    int i = blockIdx.x * TILE + t;
    int d = (i < n) ? g_deg[i] : 0;
    sh[t] = (d + 3) & ~3;
    __syncthreads();
    for (int off = TILE >> 1; off > 0; off >>= 1) {
        if (t < off) sh[t] += sh[t + off];
        __syncthreads();
    }
    if (t == 0) g_part[blockIdx.x] = sh[0];
}

__global__ void k_scan_top(int nb) {
    __shared__ int sh[512];
    int t = threadIdx.x;
    int v = (t < nb) ? g_part[t] : 0;
    sh[t] = v;
    __syncthreads();
    for (int off = 1; off < 512; off <<= 1) {
        int x = (t >= off) ? sh[t - off] : 0;
        __syncthreads();
        sh[t] += x;
        __syncthreads();
    }
    if (t < nb) g_part[t] = sh[t] - v;
}

__global__ void k_scan_fin(int n) {
    __shared__ int sh[TILE];
    int t = threadIdx.x;
    int i = blockIdx.x * TILE + t;
    int d    = (i < n) ? g_deg[i] : 0;
    int dpad = (d + 3) & ~3;
    sh[t] = dpad;
    __syncthreads();
    for (int off = 1; off < TILE; off <<= 1) {
        int x = (t >= off) ? sh[t - off] : 0;
        __syncthreads();
        sh[t] += x;
        __syncthreads();
    }
    if (i < n) {
        g_rowptr[i] = sh[t] - dpad + g_part[blockIdx.x];
        g_norm[i]   = rsqrtf(fmaxf((float)d, 1.0f));
        if (i == n - 1) g_rowptr[n] = sh[t] + g_part[blockIdx.x];
    }
}

__global__ void k_fill(const int* __restrict__ src,
                       const int* __restrict__ dst, int e, int nthreads) {
    for (int i = blockIdx.x * blockDim.x + threadIdx.x; i < e; i += nthreads) {
        int d = dst[i];
        int pos = g_rowptr[d] + atomicAdd(&g_cursor[d], 1);
        g_srcs[pos] = src[i];
    }
}

__global__ void k_pad(int n, int nthreads) {
    for (int i = blockIdx.x * blockDim.x + threadIdx.x; i < n; i += nthreads) {
        int s  = g_rowptr[i] + g_deg[i];
        int e2 = g_rowptr[i + 1];
        for (int j = s; j < e2; ++j) g_srcs[j] = n;
    }
}

__global__ void k_init(const float* __restrict__ feat, int n, int nthreads) {
    int tot = (n + 1) * DF2;
    __half2* pa = reinterpret_cast<__half2*>(g_a);
    __half2* pb = reinterpret_cast<__half2*>(g_b);
    __half2* pn = reinterpret_cast<__half2*>(g_anchor);
    for (int i = blockIdx.x * blockDim.x + threadIdx.x; i < tot; i += nthreads) {
        int row = i >> 5;
        if (row < n) {
            float nm = g_norm[row];
            float2 f = reinterpret_cast<const float2*>(feat)[i];
            pa[i] = __floats2half2_rn(nm * f.x, nm * f.y);
            pn[i] = __floats2half2_rn(0.1f * nm * f.x, 0.1f * nm * f.y);
        } else {
            __half2 z = __floats2half2_rn(0.f, 0.f);
            pa[i] = z; pb[i] = z; pn[i] = z;
        }
    }
}

// ----------------------------------------------------------------- loop ----

__device__ __forceinline__ void acc_row(const uint4& r, float* acc) {
    const __half2* h = reinterpret_cast<const __half2*>(&r);
    #pragma unroll
    for (int j = 0; j < 4; ++j) {
        float2 w = __half22float2(h[j]);
        acc[2 * j]     += w.x;
        acc[2 * j + 1] += w.y;
    }
}

// Each warp owns NPW=4 consecutive nodes, interleaved: every loop iteration
// issues 4 independent id loads then 4 independent row gathers (SIMT-4:
// one LDG.128 = four 128B fp16 rows, 8 lanes per row) before consuming any.
// Exhausted chains read the zeroed dummy row n (kept warp-uniform).
__global__ void __launch_bounds__(256) k_prop(
        const float* __restrict__ feat, float* __restrict__ out,
        int n, int flip, int last, int warps_total) {
    int wid0 = (blockIdx.x * blockDim.x + threadIdx.x) >> 5;
    int lane = threadIdx.x & 31;
    int slot = lane >> 3;
    int oct  = lane & 7;

    const uint4* gin  = flip ? g_b : g_a;
    uint4*       gout = flip ? g_a : g_b;

    int stride = warps_total * NPW;

    for (int base = wid0 * NPW; base < n; base += stride) {
        int idx[NPW], end[NPW];
        #pragma unroll
        for (int i = 0; i < NPW; ++i) {
            int v = base + i;
            if (v < n) {
                idx[i] = __ldg(&g_rowptr[v]);
                end[i] = __ldg(&g_rowptr[v + 1]);   // padded: multiple of 4
            } else {
                idx[i] = 0; end[i] = 0;
            }
        }

        float acc[NPW][8];
        #pragma unroll
        for (int i = 0; i < NPW; ++i)
            #pragma unroll
            for (int j = 0; j < 8; ++j) acc[i][j] = 0.f;

        while ((idx[0] < end[0]) | (idx[1] < end[1]) |
               (idx[2] < end[2]) | (idx[3] < end[3])) {
            int s[NPW];
            #pragma unroll
            for (int i = 0; i < NPW; ++i)
                s[i] = (idx[i] < end[i]) ? __ldg(&g_srcs[idx[i] + slot]) : n;
            uint4 r[NPW];
            #pragma unroll
            for (int i = 0; i < NPW; ++i)
                r[i] = gin[s[i] * 8 + oct];
            #pragma unroll
            for (int i = 0; i < NPW; ++i)
                acc_row(r[i], acc[i]);
            #pragma unroll
            for (int i = 0; i < NPW; ++i)
                idx[i] += 4;
        }

        // fold 4 edge-slots (lane bits 3,4) and write per node
        #pragma unroll
        for (int i = 0; i < NPW; ++i) {
            int v = base + i;
            if (v >= n) break;
            #pragma unroll
            for (int j = 0; j < 8; ++j) {
                acc[i][j] += __shfl_xor_sync(0xffffffff, acc[i][j], 8);
                acc[i][j] += __shfl_xor_sync(0xffffffff, acc[i][j], 16);
            }
            float nm = __ldg(&g_norm[v]);
            if (!last) {
                if (lane < 8) {
                    float c1 = 0.9f * nm * nm;
                    uint4 an = g_anchor[v * 8 + oct];
                    const __half2* ah = reinterpret_cast<const __half2*>(&an);
                    uint4 o;
                    __half2* oh = reinterpret_cast<__half2*>(&o);
                    #pragma unroll
                    for (int j = 0; j < 4; ++j) {
                        float2 a2 = __half22float2(ah[j]);
                        oh[j] = __floats2half2_rn(c1 * acc[i][2 * j]     + a2.x,
                                                  c1 * acc[i][2 * j + 1] + a2.y);
                    }
                    gout[v * 8 + oct] = o;
                }
            } else {
                if (lane < 8) {
                    float c1 = 0.9f * nm;
                    const float4* fr = reinterpret_cast<const float4*>(feat + v * DF);
                    float4* orow = reinterpret_cast<float4*>(out + v * DF);
                    float4 f0 = fr[oct * 2];
                    float4 f1 = fr[oct * 2 + 1];
                    float4 o0, o1;
                    o0.x = c1 * acc[i][0] + 0.1f * f0.x;
                    o0.y = c1 * acc[i][1] + 0.1f * f0.y;
                    o0.z = c1 * acc[i][2] + 0.1f * f0.z;
                    o0.w = c1 * acc[i][3] + 0.1f * f0.w;
                    o1.x = c1 * acc[i][4] + 0.1f * f1.x;
                    o1.y = c1 * acc[i][5] + 0.1f * f1.y;
                    o1.z = c1 * acc[i][6] + 0.1f * f1.z;
                    o1.w = c1 * acc[i][7] + 0.1f * f1.w;
                    orow[oct * 2]     = o0;
                    orow[oct * 2 + 1] = o1;
                }
            }
        }
    }
}

// ---------------------------------------------------------------- launch ----

extern "C" void kernel_launch(void* const* d_in, const int* in_sizes, int n_in,
                              void* d_out, int out_size) {
    const float* feat = (const float*)d_in[0];
    const int*   src  = (const int*)d_in[1];
    const int*   dst  = (const int*)d_in[2];
    float*       out  = (float*)d_out;

    int n = in_sizes[0] / DF;   // 100000
    int e = in_sizes[1];        // 1000000

    const int T = 256;
    int nb = (n + TILE - 1) / TILE;

    int dev = 0;
    cudaGetDevice(&dev);
    int sm_count = 0;
    cudaDeviceGetAttribute(&sm_count, cudaDevAttrMultiProcessorCount, dev);

    int occ_p = 0;
    cudaOccupancyMaxActiveBlocksPerMultiprocessor(&occ_p, k_prop, T, 0);
    if (occ_p < 1) occ_p = 1;
    int nblocks_p = sm_count * occ_p;
    int warps_total = (nblocks_p * T) >> 5;

    int nblocks_s = sm_count * 8;          // streaming build kernels
    int nthreads_s = nblocks_s * T;

    // CSR build with 4-padded segments (grid-stride)
    k_zero<<<nblocks_s, T>>>(n, nthreads_s);
    k_deg<<<nblocks_s, T>>>(dst, e, nthreads_s);
    k_scan_part<<<nb, TILE>>>(n);
    k_scan_top<<<1, 512>>>(nb);
    k_scan_fin<<<nb, TILE>>>(n);
    k_fill<<<nblocks_s, T>>>(src, dst, e, nthreads_s);
    k_pad<<<nblocks_s, T>>>(n, nthreads_s);
    k_init<<<nblocks_s, T>>>(feat, n, nthreads_s);

    // Propagation: ping-pong g_a <-> g_b, final iter writes d_out (fp32).
    for (int t = 0; t < KITER; ++t) {
        int flip = t & 1;
        int last = (t == KITER - 1);
        k_prop<<<nblocks_p, T>>>(feat, out, n, flip, last, warps_total);
    }
}

// round 12
// speedup vs baseline: 1.0869x; 1.0869x over previous
#include <cuda_runtime.h>
#include <cuda_fp16.h>

// APPNP, K=10. State g = norm ⊙ h in fp16 (row = 64 halves = 128B).
//   g_{t+1} = 0.9*norm^2 * (sum_{(s->v)} g_t[s]) + anchor, anchor = 0.1*norm*feat
// Final: h = 0.9*norm*agg + 0.1*feat (fp32).
//
// Round 12: hot-loop instruction diet. The fp16 loop is hypothesized
// convert-bound (F2F slow class): pair-sum the two gathered rows with HADD2
// (cheap fixed-lat) BEFORE converting, halving F2F and FADD counts.
// Structure otherwise = round 8 best (one warp/node, SIMT-4 gather,
// 4-padded CSR, per-iteration launches). k_pad fused into k_init.

#define NMAX  100000
#define DF    64
#define DF2   (DF / 2)
#define EMAX  1000000
#define EPAD  (EMAX + 4 * NMAX + 32)
#define KITER 10
#define TILE  256
#define NTILE ((NMAX + TILE - 1) / TILE)   // 391

__device__ uint4 g_a[(NMAX + 1) * 8];
__device__ uint4 g_b[(NMAX + 1) * 8];
__device__ uint4 g_anchor[(NMAX + 1) * 8];  // 0.1*norm*feat in fp16
__device__ float g_norm[NMAX];
__device__ int   g_deg[NMAX];
__device__ int   g_rowptr[NMAX + 1];        // padded-degree prefix
__device__ int   g_cursor[NMAX];
__device__ int   g_srcs[EPAD];
__device__ int   g_part[NTILE];

// ---------------------------------------------------------------- build ----

__global__ void k_zero(int n, int nthreads) {
    for (int i = blockIdx.x * blockDim.x + threadIdx.x; i < n; i += nthreads) {
        g_deg[i] = 0; g_cursor[i] = 0;
    }
}

__global__ void k_deg(const int* __restrict__ dst, int e, int nthreads) {
    for (int i = blockIdx.x * blockDim.x + threadIdx.x; i < e; i += nthreads)
        atomicAdd(&g_deg[dst[i]], 1);
}

__global__ void k_scan_part(int n) {
    __shared__ int sh[TILE];
    int t = threadIdx.x;
    int i = blockIdx.x * TILE + t;
    int d = (i < n) ? g_deg[i] : 0;
    sh[t] = (d + 3) & ~3;
    __syncthreads();
    for (int off = TILE >> 1; off > 0; off >>= 1) {
        if (t < off) sh[t] += sh[t + off];
        __syncthreads();
    }
    if (t == 0) g_part[blockIdx.x] = sh[0];
}

__global__ void k_scan_top(int nb) {
    __shared__ int sh[512];
    int t = threadIdx.x;
    int v = (t < nb) ? g_part[t] : 0;
    sh[t] = v;
    __syncthreads();
    for (int off = 1; off < 512; off <<= 1) {
        int x = (t >= off) ? sh[t - off] : 0;
        __syncthreads();
        sh[t] += x;
        __syncthreads();
    }
    if (t < nb) g_part[t] = sh[t] - v;
}

__global__ void k_scan_fin(int n) {
    __shared__ int sh[TILE];
    int t = threadIdx.x;
    int i = blockIdx.x * TILE + t;
    int d    = (i < n) ? g_deg[i] : 0;
    int dpad = (d + 3) & ~3;
    sh[t] = dpad;
    __syncthreads();
    for (int off = 1; off < TILE; off <<= 1) {
        int x = (t >= off) ? sh[t - off] : 0;
        __syncthreads();
        sh[t] += x;
        __syncthreads();
    }
    if (i < n) {
        g_rowptr[i] = sh[t] - dpad + g_part[blockIdx.x];
        g_norm[i]   = rsqrtf(fmaxf((float)d, 1.0f));
        if (i == n - 1) g_rowptr[n] = sh[t] + g_part[blockIdx.x];
    }
}

__global__ void k_fill(const int* __restrict__ src,
                       const int* __restrict__ dst, int e, int nthreads) {
    for (int i = blockIdx.x * blockDim.x + threadIdx.x; i < e; i += nthreads) {
        int d = dst[i];
        int pos = g_rowptr[d] + atomicAdd(&g_cursor[d], 1);
        g_srcs[pos] = src[i];
    }
}

// init state/anchor, zero dummy row, AND fill pad slots (fused k_pad).
__global__ void k_init(const float* __restrict__ feat, int n, int nthreads) {
    int tot = (n + 1) * DF2;
    __half2* pa = reinterpret_cast<__half2*>(g_a);
    __half2* pb = reinterpret_cast<__half2*>(g_b);
    __half2* pn = reinterpret_cast<__half2*>(g_anchor);
    int t0 = blockIdx.x * blockDim.x + threadIdx.x;
    for (int i = t0; i < tot; i += nthreads) {
        int row = i >> 5;
        if (row < n) {
            float nm = g_norm[row];
            float2 f = reinterpret_cast<const float2*>(feat)[i];
            pa[i] = __floats2half2_rn(nm * f.x, nm * f.y);
            pn[i] = __floats2half2_rn(0.1f * nm * f.x, 0.1f * nm * f.y);
        } else {
            __half2 z = __floats2half2_rn(0.f, 0.f);
            pa[i] = z; pb[i] = z; pn[i] = z;
        }
    }
    for (int i = t0; i < n; i += nthreads) {
        int s  = g_rowptr[i] + g_deg[i];
        int e2 = g_rowptr[i + 1];
        for (int j = s; j < e2; ++j) g_srcs[j] = n;
    }
}

// ----------------------------------------------------------------- loop ----

__device__ __forceinline__ void acc_row(const uint4& r, float* acc) {
    const __half2* h = reinterpret_cast<const __half2*>(&r);
    #pragma unroll
    for (int j = 0; j < 4; ++j) {
        float2 w = __half22float2(h[j]);
        acc[2 * j]     += w.x;
        acc[2 * j + 1] += w.y;
    }
}

// Pair-sum two rows in fp16 (HADD2), then convert+accumulate once.
__device__ __forceinline__ void acc_row_pair(const uint4& r0, const uint4& r1,
                                             float* acc) {
    const __half2* h0 = reinterpret_cast<const __half2*>(&r0);
    const __half2* h1 = reinterpret_cast<const __half2*>(&r1);
    #pragma unroll
    for (int j = 0; j < 4; ++j) {
        __half2 p = __hadd2(h0[j], h1[j]);
        float2 w = __half22float2(p);
        acc[2 * j]     += w.x;
        acc[2 * j + 1] += w.y;
    }
}

// One warp per node; SIMT-4 gather (one LDG.128 = four 128B fp16 rows,
// 8 lanes per row); fp32 partials; xor-shuffle fold at the end.
__global__ void __launch_bounds__(256) k_prop(
        const float* __restrict__ feat, float* __restrict__ out,
        int n, int flip, int last) {
    int gt   = blockIdx.x * blockDim.x + threadIdx.x;
    int v    = gt >> 5;
    int lane = gt & 31;
    if (v >= n) return;

    const uint4* gin  = flip ? g_b : g_a;
    uint4*       gout = flip ? g_a : g_b;

    int idx = __ldg(&g_rowptr[v]);
    int end = __ldg(&g_rowptr[v + 1]);   // padded: multiple of 4

    int slot = lane >> 3;
    int oct  = lane & 7;

    float acc[8];
    #pragma unroll
    for (int j = 0; j < 8; ++j) acc[j] = 0.f;

    for (; idx + 8 <= end; idx += 8) {
        int s0 = __ldg(&g_srcs[idx + slot]);
        int s1 = __ldg(&g_srcs[idx + 4 + slot]);
        uint4 r0 = gin[s0 * 8 + oct];
        uint4 r1 = gin[s1 * 8 + oct];
        acc_row_pair(r0, r1, acc);        // HADD2 pair-sum, half the converts
    }
    if (idx < end) {
        int s0 = __ldg(&g_srcs[idx + slot]);
        uint4 r0 = gin[s0 * 8 + oct];
        acc_row(r0, acc);
    }

    #pragma unroll
    for (int j = 0; j < 8; ++j) {
        acc[j] += __shfl_xor_sync(0xffffffff, acc[j], 8);
        acc[j] += __shfl_xor_sync(0xffffffff, acc[j], 16);
    }

    float nm = __ldg(&g_norm[v]);

    if (!last) {
        if (lane < 8) {
            float c1 = 0.9f * nm * nm;
            uint4 an = g_anchor[v * 8 + oct];
            const __half2* ah = reinterpret_cast<const __half2*>(&an);
            uint4 o;
            __half2* oh = reinterpret_cast<__half2*>(&o);
            #pragma unroll
            for (int j = 0; j < 4; ++j) {
                float2 a2 = __half22float2(ah[j]);
                oh[j] = __floats2half2_rn(c1 * acc[2 * j]     + a2.x,
                                          c1 * acc[2 * j + 1] + a2.y);
            }
            gout[v * 8 + oct] = o;
        }
    } else {
        if (lane < 8) {
            float c1 = 0.9f * nm;
            const float4* fr = reinterpret_cast<const float4*>(feat + v * DF);
            float4* orow = reinterpret_cast<float4*>(out + v * DF);
            float4 f0 = fr[oct * 2];
            float4 f1 = fr[oct * 2 + 1];
            float4 o0, o1;
            o0.x = c1 * acc[0] + 0.1f * f0.x;
            o0.y = c1 * acc[1] + 0.1f * f0.y;
            o0.z = c1 * acc[2] + 0.1f * f0.z;
            o0.w = c1 * acc[3] + 0.1f * f0.w;
            o1.x = c1 * acc[4] + 0.1f * f1.x;
            o1.y = c1 * acc[5] + 0.1f * f1.y;
            o1.z = c1 * acc[6] + 0.1f * f1.z;
            o1.w = c1 * acc[7] + 0.1f * f1.w;
            orow[oct * 2]     = o0;
            orow[oct * 2 + 1] = o1;
        }
    }
}

// ---------------------------------------------------------------- launch ----

extern "C" void kernel_launch(void* const* d_in, const int* in_sizes, int n_in,
                              void* d_out, int out_size) {
    const float* feat = (const float*)d_in[0];
    const int*   src  = (const int*)d_in[1];
    const int*   dst  = (const int*)d_in[2];
    float*       out  = (float*)d_out;

    int n = in_sizes[0] / DF;   // 100000
    int e = in_sizes[1];        // 1000000

    const int T = 256;
    int nb = (n + TILE - 1) / TILE;
    int blk_p = (n * 32 + T - 1) / T;       // warp per node

    int dev = 0;
    cudaGetDevice(&dev);
    int sm_count = 0;
    cudaDeviceGetAttribute(&sm_count, cudaDevAttrMultiProcessorCount, dev);
    int nblocks_s = sm_count * 8;
    int nthreads_s = nblocks_s * T;

    // CSR build with 4-padded segments
    k_zero<<<nblocks_s, T>>>(n, nthreads_s);
    k_deg<<<nblocks_s, T>>>(dst, e, nthreads_s);
    k_scan_part<<<nb, TILE>>>(n);
    k_scan_top<<<1, 512>>>(nb);
    k_scan_fin<<<nb, TILE>>>(n);
    k_fill<<<nblocks_s, T>>>(src, dst, e, nthreads_s);
    k_init<<<nblocks_s, T>>>(feat, n, nthreads_s);

    // Propagation: ping-pong g_a <-> g_b, final iter writes d_out (fp32).
    for (int t = 0; t < KITER; ++t) {
        int flip = t & 1;
        int last = (t == KITER - 1);
        k_prop<<<blk_p, T>>>(feat, out, n, flip, last);
    }
}